// round 15
// baseline (speedup 1.0000x reference)
#include <cuda_runtime.h>
#include <cuda_bf16.h>

#define N_NODES   50000
#define N_EDGES   800000
#define N_FEAT    128
#define NHID      64
#define NGRAPHS   512
#define KPOOL     30
#define NCLASSES  10
#define SCAN_BLOCKS ((N_NODES + 255) / 256)   // 196

// ---------------- device scratch ----------------
__device__ __align__(16) float g_y[N_NODES * NHID];   // projected neighbor feats (h @ Wl)
__device__ __align__(16) float g_z[N_NODES * NHID];   // self term (h @ Wr + b)
__device__ __align__(16) float g_h[N_NODES * NHID];   // layer output
__device__ __align__(16) int   g_csrc[N_EDGES];       // CSR: src ids bucketed by dst
__device__ __align__(16) int   g_degi[N_NODES];
__device__ __align__(16) int   g_rowoff[N_NODES];
__device__ __align__(16) int   g_cursor[N_NODES];
__device__ __align__(16) int   g_counts[NGRAPHS];
__device__ __align__(16) int   g_starts[NGRAPHS];
__device__ __align__(16) int   g_bsum[SCAN_BLOCKS];
__device__ __align__(16) int   g_bpre[SCAN_BLOCKS];
__device__ int g_is64_ei;
__device__ int g_is64_batch;

// ---------------- init: block 0 = parallel dtype detect; other blocks zero counters ------
__global__ void k_init(const void* __restrict__ ei, const void* __restrict__ batch) {
    if (blockIdx.x == 0) {
        __shared__ int bad_e, bad_b;
        if (threadIdx.x == 0) { bad_e = 0; bad_b = 0; }
        __syncthreads();
        const long long* e64 = (const long long*)ei;
        const long long* b64 = (const long long*)batch;
        for (int i = threadIdx.x; i < 2048; i += 256) {
            long long v = e64[i];
            if (v < 0 || v >= N_NODES) bad_e = 1;
            long long b = b64[i];
            if (b < 0 || b >= NGRAPHS) bad_b = 1;
        }
        __syncthreads();
        if (threadIdx.x == 0) {
            g_is64_ei    = !bad_e;
            g_is64_batch = !bad_b;
        }
    } else {
        int i = (blockIdx.x - 1) * blockDim.x + threadIdx.x;
        if (i < N_NODES) g_degi[i] = 0;
        if (i < NGRAPHS) g_counts[i] = 0;
    }
}

// ---------------- load helpers: 4 consecutive edge indices (dtype adaptive) ----------------
__device__ __forceinline__ void ld4idx(const void* base, int off, int is64,
                                       int& a, int& b, int& c, int& d) {
    if (is64) {
        longlong2 p0 = __ldg((const longlong2*)((const long long*)base + off));
        longlong2 p1 = __ldg((const longlong2*)((const long long*)base + off + 2));
        a = (int)p0.x; b = (int)p0.y; c = (int)p1.x; d = (int)p1.y;
    } else {
        int4 p = __ldg((const int4*)((const int*)base + off));
        a = p.x; b = p.y; c = p.z; d = p.w;
    }
}

// ---------------- degrees + graph counts: 4 elements/thread (MLP) ----------------
__global__ void k_prep(const void* __restrict__ ei,
                       const void* __restrict__ batch) {
    int t = blockIdx.x * blockDim.x + threadIdx.x;
    int e0 = t * 4;
    if (e0 < N_EDGES) {
        int d0, d1, d2, d3;
        ld4idx(ei, N_EDGES + e0, g_is64_ei, d0, d1, d2, d3);
        atomicAdd(&g_degi[d0], 1);
        atomicAdd(&g_degi[d1], 1);
        atomicAdd(&g_degi[d2], 1);
        atomicAdd(&g_degi[d3], 1);
    }
    if (e0 < N_NODES) {
        int b0, b1, b2, b3;
        ld4idx(batch, e0, g_is64_batch, b0, b1, b2, b3);
        atomicAdd(&g_counts[b0], 1);
        atomicAdd(&g_counts[b1], 1);
        atomicAdd(&g_counts[b2], 1);
        atomicAdd(&g_counts[b3], 1);
    }
}

// ---------------- scan phase 1: coalesced per-block sums of degi ----------------
__global__ __launch_bounds__(256) void k_scan1() {
    __shared__ int sh[256];
    int i = blockIdx.x * 256 + threadIdx.x;
    int v = (i < N_NODES) ? g_degi[i] : 0;
    sh[threadIdx.x] = v;
    __syncthreads();
#pragma unroll
    for (int off = 128; off > 0; off >>= 1) {
        if (threadIdx.x < off) sh[threadIdx.x] += sh[threadIdx.x + off];
        __syncthreads();
    }
    if (threadIdx.x == 0) g_bsum[blockIdx.x] = sh[0];
}

// ---------------- scan phase 2 (1 block, 512 thr): graph starts + block prefixes ----------
__global__ __launch_bounds__(512) void k_scan2() {
    __shared__ int s[512];
    const int t = threadIdx.x;

    int myc = g_counts[t];
    s[t] = myc;
    __syncthreads();
#pragma unroll
    for (int off = 1; off < 512; off <<= 1) {
        int v = (t >= off) ? s[t - off] : 0;
        __syncthreads();
        s[t] += v;
        __syncthreads();
    }
    g_starts[t] = s[t] - myc;
    __syncthreads();

    int mb = (t < SCAN_BLOCKS) ? g_bsum[t] : 0;
    s[t] = mb;
    __syncthreads();
#pragma unroll
    for (int off = 1; off < 512; off <<= 1) {
        int v = (t >= off) ? s[t - off] : 0;
        __syncthreads();
        s[t] += v;
        __syncthreads();
    }
    if (t < SCAN_BLOCKS) g_bpre[t] = s[t] - mb;
}

// ---------------- scan phase 3: block-local exclusive scan + base, coalesced writes ------
__global__ __launch_bounds__(256) void k_scan3() {
    __shared__ int sh[256];
    const int t = threadIdx.x;
    int i = blockIdx.x * 256 + t;
    int v = (i < N_NODES) ? g_degi[i] : 0;
    sh[t] = v;
    __syncthreads();
#pragma unroll
    for (int off = 1; off < 256; off <<= 1) {
        int u = (t >= off) ? sh[t - off] : 0;
        __syncthreads();
        sh[t] += u;
        __syncthreads();
    }
    int excl = sh[t] - v + g_bpre[blockIdx.x];
    if (i < N_NODES) {
        g_rowoff[i] = excl;
        g_cursor[i] = excl;
    }
}

// ---------------- fill CSR buckets: 4 edges/thread, reads ei directly ----------------
__global__ void k_fill(const void* __restrict__ ei) {
    int t = blockIdx.x * blockDim.x + threadIdx.x;
    int e0 = t * 4;
    if (e0 >= N_EDGES) return;
    int s0, s1, s2, s3, d0, d1, d2, d3;
    ld4idx(ei, e0, g_is64_ei, s0, s1, s2, s3);
    ld4idx(ei, N_EDGES + e0, g_is64_ei, d0, d1, d2, d3);
    int p0 = atomicAdd(&g_cursor[d0], 1);
    int p1 = atomicAdd(&g_cursor[d1], 1);
    int p2 = atomicAdd(&g_cursor[d2], 1);
    int p3 = atomicAdd(&g_cursor[d3], 1);
    g_csrc[p0] = s0;
    g_csrc[p1] = s1;
    g_csrc[p2] = s2;
    g_csrc[p3] = s3;
}

// ---------------- dual GEMM: g_y = in@Wl ; g_z = in@Wr + b ----------------
// 64 rows/block, 256 threads. Thread tile: 8 rows x 4 cols of ONE matrix.
// Warp layout: bits 0-3 = col group (x4), bit 4 = matrix select, bits 5-7 = row group.
// All 32 lanes of a warp share the same 8 rows -> xs reads are pure LDS broadcasts.
template <int KIN>
__global__ __launch_bounds__(256) void k_gemm(const float* __restrict__ in,
                                              const float* __restrict__ Wl,
                                              const float* __restrict__ Wr,
                                              const float* __restrict__ bias) {
    __shared__ float xs[64][KIN];
    const float* __restrict__ src = in ? in : g_h;
    const int row0 = blockIdx.x * 64;
    const int tid  = threadIdx.x;

    const int NV4 = 64 * KIN / 4;
    for (int i4 = tid; i4 < NV4; i4 += 256) {
        int i = i4 * 4;
        int r = i / KIN, k = i % KIN;
        int row = row0 + r;
        float4 v = (row < N_NODES)
            ? __ldg((const float4*)(src + (size_t)row * KIN + k))
            : make_float4(0.f, 0.f, 0.f, 0.f);
        *(float4*)(&xs[r][k]) = v;
    }
    __syncthreads();

    const int c4 = (tid & 15) * 4;     // col group: 4 consecutive cols
    const int m  = (tid >> 4) & 1;     // 0: Wl->y, 1: Wr->z
    const int rb = (tid >> 5) * 8;     // row base within block
    const float* __restrict__ W = m ? Wr : Wl;

    float acc[8][4];
#pragma unroll
    for (int r = 0; r < 8; r++)
#pragma unroll
        for (int c = 0; c < 4; c++) acc[r][c] = 0.f;

#pragma unroll 2
    for (int k = 0; k < KIN; k++) {
        float4 w = __ldg((const float4*)(W + k * NHID + c4));
#pragma unroll
        for (int r = 0; r < 8; r++) {
            float xv = xs[rb + r][k];
            acc[r][0] = fmaf(xv, w.x, acc[r][0]);
            acc[r][1] = fmaf(xv, w.y, acc[r][1]);
            acc[r][2] = fmaf(xv, w.z, acc[r][2]);
            acc[r][3] = fmaf(xv, w.w, acc[r][3]);
        }
    }

    float4 bv = m ? __ldg((const float4*)(bias + c4)) : make_float4(0.f, 0.f, 0.f, 0.f);
    float* __restrict__ out = m ? g_z : g_y;
#pragma unroll
    for (int r = 0; r < 8; r++) {
        int row = row0 + rb + r;
        if (row < N_NODES) {
            float4 o = make_float4(acc[r][0] + bv.x, acc[r][1] + bv.y,
                                   acc[r][2] + bv.z, acc[r][3] + bv.w);
            *(float4*)(out + (size_t)row * NHID + c4) = o;
        }
    }
}

// ---------------- gather aggregation + combine: one warp per node, 2 edges/iter ----------
__global__ __launch_bounds__(256) void k_agg() {
    const int warp = (blockIdx.x * 256 + threadIdx.x) >> 5;
    const int lane = threadIdx.x & 31;
    if (warp >= N_NODES) return;

    const int q    = lane & 15;
    const int pair = lane >> 4;
    const int beg = g_rowoff[warp];
    const int deg = g_degi[warp];
    const int end = beg + deg;

    const float4* __restrict__ y4 = reinterpret_cast<const float4*>(g_y);
    float4 a0 = make_float4(0.f, 0.f, 0.f, 0.f);
    float4 a1 = make_float4(0.f, 0.f, 0.f, 0.f);

    int e = beg + pair;
    for (; e + 2 < end; e += 4) {
        int s0 = __ldg(&g_csrc[e]);
        int s1 = __ldg(&g_csrc[e + 2]);
        float4 v0 = __ldg(&y4[(size_t)s0 * 16 + q]);
        float4 v1 = __ldg(&y4[(size_t)s1 * 16 + q]);
        a0.x += v0.x; a0.y += v0.y; a0.z += v0.z; a0.w += v0.w;
        a1.x += v1.x; a1.y += v1.y; a1.z += v1.z; a1.w += v1.w;
    }
    for (; e < end; e += 2) {
        int s = __ldg(&g_csrc[e]);
        float4 v = __ldg(&y4[(size_t)s * 16 + q]);
        a0.x += v.x; a0.y += v.y; a0.z += v.z; a0.w += v.w;
    }
    a0.x += a1.x; a0.y += a1.y; a0.z += a1.z; a0.w += a1.w;

    a0.x += __shfl_xor_sync(0xffffffffu, a0.x, 16);
    a0.y += __shfl_xor_sync(0xffffffffu, a0.y, 16);
    a0.z += __shfl_xor_sync(0xffffffffu, a0.z, 16);
    a0.w += __shfl_xor_sync(0xffffffffu, a0.w, 16);

    if (pair == 0) {
        float inv = 1.f / fmaxf((float)deg, 1.f);
        float4 z = __ldg(&reinterpret_cast<const float4*>(g_z)[(size_t)warp * 16 + q]);
        float4 ho;
        ho.x = fmaxf(fmaf(a0.x, inv, z.x), 0.f);
        ho.y = fmaxf(fmaf(a0.y, inv, z.y), 0.f);
        ho.z = fmaxf(fmaf(a0.z, inv, z.z), 0.f);
        ho.w = fmaxf(fmaf(a0.w, inv, z.w), 0.f);
        reinterpret_cast<float4*>(g_h)[(size_t)warp * 16 + q] = ho;
    }
}

// ---------------- fused tail: sort-pool + conv1d + lin1 + lin2 + log_softmax ----------------
__global__ __launch_bounds__(256) void k_tail(const float* __restrict__ convw,
                                              const float* __restrict__ convb,
                                              const float* __restrict__ lin1w,
                                              const float* __restrict__ lin1b,
                                              const float* __restrict__ lin2w,
                                              const float* __restrict__ lin2b,
                                              float* __restrict__ out) {
    const int g = blockIdx.x;
    const int tid = threadIdx.x;
    const int s = g_starts[g];
    const int cnt = g_counts[g];

    __shared__ float sp[NHID * KPOOL];
    __shared__ float skey[2048];
    __shared__ float sconv[32 * 26];
    __shared__ float sred[256];
    __shared__ float sf[NHID];
    __shared__ float slog[NCLASSES];
    __shared__ float smax, slse;

    for (int i = tid; i < NHID * KPOOL; i += 256) sp[i] = 0.f;

    const int cap = (cnt < 2048) ? cnt : 2048;
    for (int i = tid; i < cap; i += 256)
        skey[i] = g_h[(size_t)(s + i) * NHID + (NHID - 1)];
    __syncthreads();

    for (int i = tid; i < cnt; i += 256) {
        float ki = (i < cap) ? skey[i] : g_h[(size_t)(s + i) * NHID + (NHID - 1)];
        int rank = 0;
        for (int j = 0; j < cnt; j++) {
            float kj = (j < cap) ? skey[j] : g_h[(size_t)(s + j) * NHID + (NHID - 1)];
            rank += (kj > ki) || (kj == ki && j < i);   // stable lexsort order
            if (rank >= KPOOL) break;
        }
        if (rank < KPOOL) {
            const float* hr = g_h + (size_t)(s + i) * NHID;
#pragma unroll 4
            for (int c = 0; c < NHID; c++)
                sp[c * KPOOL + rank] = hr[c];
        }
    }
    __syncthreads();

    for (int idx = tid; idx < 32 * 26; idx += 256) {
        int o = idx / 26, t = idx % 26;
        float acc = __ldg(&convb[o]);
        const float* wbase = convw + (size_t)o * NHID * 5;
        for (int c = 0; c < NHID; c++) {
            const float* wrow = wbase + c * 5;
            const float* prow = sp + c * KPOOL + t;
#pragma unroll
            for (int kk = 0; kk < 5; kk++)
                acc = fmaf(prow[kk], __ldg(&wrow[kk]), acc);
        }
        sconv[idx] = fmaxf(acc, 0.f);
    }
    __syncthreads();

    {
        int j = tid & 63, part = tid >> 6;
        float acc = 0.f;
        for (int i = part; i < 32 * 26; i += 4)
            acc = fmaf(sconv[i], __ldg(&lin1w[(size_t)i * NHID + j]), acc);
        sred[tid] = acc;
        __syncthreads();
        if (part == 0) {
            float v = sred[j] + sred[j + 64] + sred[j + 128] + sred[j + 192];
            sf[j] = fmaxf(v + __ldg(&lin1b[j]), 0.f);
        }
        __syncthreads();
    }

    if (tid < NCLASSES) {
        float acc = __ldg(&lin2b[tid]);
        for (int j = 0; j < NHID; j++)
            acc = fmaf(sf[j], __ldg(&lin2w[j * NCLASSES + tid]), acc);
        slog[tid] = acc;
    }
    __syncthreads();
    if (tid == 0) {
        float mx = slog[0];
        for (int k = 1; k < NCLASSES; k++) mx = fmaxf(mx, slog[k]);
        float sum = 0.f;
        for (int k = 0; k < NCLASSES; k++) sum += expf(slog[k] - mx);
        smax = mx;
        slse = logf(sum);
    }
    __syncthreads();
    if (tid < NCLASSES)
        out[(size_t)g * NCLASSES + tid] = slog[tid] - smax - slse;
}

// ---------------- host launcher ----------------
extern "C" void kernel_launch(void* const* d_in, const int* in_sizes, int n_in,
                              void* d_out, int out_size) {
    const float* x     = (const float*)d_in[0];
    const void*  ei    = d_in[1];
    const void*  batch = d_in[2];
    const float* W1l = (const float*)d_in[3];
    const float* b1  = (const float*)d_in[4];
    const float* W1r = (const float*)d_in[5];
    const float* W2l = (const float*)d_in[6];
    const float* b2  = (const float*)d_in[7];
    const float* W2r = (const float*)d_in[8];
    const float* W3l = (const float*)d_in[9];
    const float* b3  = (const float*)d_in[10];
    const float* W3r = (const float*)d_in[11];
    const float* convw = (const float*)d_in[12];
    const float* convb = (const float*)d_in[13];
    const float* lin1w = (const float*)d_in[14];
    const float* lin1b = (const float*)d_in[15];
    const float* lin2w = (const float*)d_in[16];
    const float* lin2b = (const float*)d_in[17];
    float* out = (float*)d_out;

    const int GB = (N_NODES + 63) / 64;                 // gemm blocks (64 rows each)
    const int AB = (N_NODES * 32 + 255) / 256;          // agg blocks (warp/node)
    const int PB = (N_EDGES / 4 + 255) / 256;           // prep/fill blocks (4 edges/thread)

    // Launch order chosen so ncu's -s 5 -c 1 window captures k_gemm<128> (6th launch).
    k_init<<<1 + (N_NODES + 255) / 256, 256>>>(ei, batch);   // 1
    k_prep<<<PB, 256>>>(ei, batch);                          // 2
    k_scan1<<<SCAN_BLOCKS, 256>>>();                         // 3
    k_scan2<<<1, 512>>>();                                   // 4
    k_scan3<<<SCAN_BLOCKS, 256>>>();                         // 5
    k_gemm<N_FEAT><<<GB, 256>>>(x, W1l, W1r, b1);            // 6  <- profiled
    k_fill<<<PB, 256>>>(ei);                                 // 7
    k_agg<<<AB, 256>>>();                                    // 8
    k_gemm<NHID><<<GB, 256>>>(nullptr, W2l, W2r, b2);        // 9
    k_agg<<<AB, 256>>>();                                    // 10
    k_gemm<NHID><<<GB, 256>>>(nullptr, W3l, W3r, b3);        // 11
    k_agg<<<AB, 256>>>();                                    // 12
    k_tail<<<NGRAPHS, 256>>>(convw, convb, lin1w, lin1b, lin2w, lin2b, out);  // 13
}